// round 16
// baseline (speedup 1.0000x reference)
#include <cuda_runtime.h>
#include <cstdint>
#include <math.h>

#define NN 50000
#define EE 800000
#define DD 128
#define KK 64
#define BN_EPS_F 1e-5f
#define SCAN_NB 49

// ---------------- scratch (static device memory) ----------------
__device__ float  g_agg[NN * DD];
__device__ float  g_h[NN * DD];
__device__ double g_stats[4 * DD];
__device__ float  g_scale[DD];
__device__ float  g_shift[DD];
// CSR
__device__ int g_deg[NN], g_off[NN + 1], g_cursor[NN], g_csr[EE], g_bsum[SCAN_NB];
__device__ int g_scan_ctr;
__device__ int g_mlp_ctr[2];

// ---------------- zero degree + stats + counters ----------------
__global__ void k_zero() {
    int i = blockIdx.x * blockDim.x + threadIdx.x;
    if (i < NN) g_deg[i] = 0;
    if (i < 512) g_stats[i] = 0.0;
    if (i == 512) g_scan_ctr = 0;
    if (i == 513) g_mlp_ctr[0] = 0;
    if (i == 514) g_mlp_ctr[1] = 0;
}

// ---------------- in-degree histogram: 4 edges/thread, int4 loads ----------------
__global__ void k_hist(const int* __restrict__ ei) {
    int e4 = blockIdx.x * blockDim.x + threadIdx.x;
    if (e4 >= EE / 4) return;
    int4 d = __ldg((const int4*)(ei + EE) + e4);
    if ((unsigned)d.x < NN) atomicAdd(&g_deg[d.x], 1);
    if ((unsigned)d.y < NN) atomicAdd(&g_deg[d.y], 1);
    if ((unsigned)d.z < NN) atomicAdd(&g_deg[d.z], 1);
    if ((unsigned)d.w < NN) atomicAdd(&g_deg[d.w], 1);
}

// ---------------- fused exclusive scan (single kernel, grid spin barrier) ----------------
__global__ void __launch_bounds__(1024) k_scan() {
    __shared__ int swarp[32];
    __shared__ int partial[2];
    int b = blockIdx.x, tid = threadIdx.x;
    int lane = tid & 31, w = tid >> 5;
    int i = b * 1024 + tid;

    int v = (i < NN) ? g_deg[i] : 0;
    int xv = v;
    #pragma unroll
    for (int o = 1; o < 32; o <<= 1) {
        int y = __shfl_up_sync(0xffffffffu, xv, o);
        if (lane >= o) xv += y;
    }
    if (lane == 31) swarp[w] = xv;
    __syncthreads();
    if (w == 0) {
        int y = swarp[lane];
        #pragma unroll
        for (int o = 1; o < 32; o <<= 1) {
            int z = __shfl_up_sync(0xffffffffu, y, o);
            if (lane >= o) y += z;
        }
        swarp[lane] = y;
    }
    __syncthreads();
    int excl = xv - v + (w > 0 ? swarp[w - 1] : 0);
    if (tid == 1023) {
        g_bsum[b] = excl + v;
        __threadfence();
    }
    __syncthreads();

    if (tid == 0) {
        atomicAdd(&g_scan_ctr, 1);
        while (atomicAdd(&g_scan_ctr, 0) < SCAN_NB) { }
    }
    __syncthreads();
    __threadfence();

    int pv = 0;
    if (tid < 64) {
        if (tid < SCAN_NB && tid < b) pv = g_bsum[tid];
        #pragma unroll
        for (int o = 16; o > 0; o >>= 1) pv += __shfl_down_sync(0xffffffffu, pv, o);
        if ((tid & 31) == 0) partial[tid >> 5] = pv;
    }
    __syncthreads();
    int base = partial[0] + partial[1];
    if (i < NN) {
        int o = excl + base;
        g_off[i] = o;
        g_cursor[i] = o;
    }
    if (b == SCAN_NB - 1 && tid == 0) g_off[NN] = base + g_bsum[b];
}

// ---------------- permute: 4 edges/thread, int4 loads ----------------
__global__ void k_permute(const int* __restrict__ ei) {
    int e4 = blockIdx.x * blockDim.x + threadIdx.x;
    if (e4 >= EE / 4) return;
    int4 s = __ldg((const int4*)ei + e4);
    int4 d = __ldg((const int4*)(ei + EE) + e4);
    if ((unsigned)s.x < NN && (unsigned)d.x < NN) g_csr[atomicAdd(&g_cursor[d.x], 1)] = s.x;
    if ((unsigned)s.y < NN && (unsigned)d.y < NN) g_csr[atomicAdd(&g_cursor[d.y], 1)] = s.y;
    if ((unsigned)s.z < NN && (unsigned)d.z < NN) g_csr[atomicAdd(&g_cursor[d.z], 1)] = s.z;
    if ((unsigned)s.w < NN && (unsigned)d.w < NN) g_csr[atomicAdd(&g_cursor[d.w], 1)] = s.w;
}

// ---------------- gather (layer 1): agg[n] = (1+eps)*x[n] + sum x[j] ----------------
__global__ void k_gather(const float* __restrict__ feat, const float* __restrict__ epsp) {
    int gw = (blockIdx.x * blockDim.x + threadIdx.x) >> 5;
    int lane = threadIdx.x & 31;
    if (gw >= NN) return;
    float e = 1.0f + *epsp;
    float4 acc = __ldg((const float4*)(feat + (size_t)gw * DD) + lane);
    acc.x *= e; acc.y *= e; acc.z *= e; acc.w *= e;
    int beg = __ldg(&g_off[gw]);
    int end = __ldg(&g_off[gw + 1]);
    int j = beg;
    for (; j + 4 <= end; j += 4) {
        int s0 = __ldg(&g_csr[j]);
        int s1 = __ldg(&g_csr[j + 1]);
        int s2 = __ldg(&g_csr[j + 2]);
        int s3 = __ldg(&g_csr[j + 3]);
        float4 v0 = __ldg((const float4*)(feat + (size_t)s0 * DD) + lane);
        float4 v1 = __ldg((const float4*)(feat + (size_t)s1 * DD) + lane);
        float4 v2 = __ldg((const float4*)(feat + (size_t)s2 * DD) + lane);
        float4 v3 = __ldg((const float4*)(feat + (size_t)s3 * DD) + lane);
        acc.x += (v0.x + v1.x) + (v2.x + v3.x);
        acc.y += (v0.y + v1.y) + (v2.y + v3.y);
        acc.z += (v0.z + v1.z) + (v2.z + v3.z);
        acc.w += (v0.w + v1.w) + (v2.w + v3.w);
    }
    for (; j < end; j++) {
        int s = __ldg(&g_csr[j]);
        float4 v = __ldg((const float4*)(feat + (size_t)s * DD) + lane);
        acc.x += v.x; acc.y += v.y; acc.z += v.z; acc.w += v.w;
    }
    ((float4*)(g_agg + (size_t)gw * DD))[lane] = acc;
}

// ---------------- gather layer 2: fused BN+relu (scale/shift globals), reads g_h ----------------
__global__ void k_gather_bn(const float* __restrict__ epsp) {
    int gw = (blockIdx.x * blockDim.x + threadIdx.x) >> 5;
    int lane = threadIdx.x & 31;
    if (gw >= NN) return;
    float e = 1.0f + *epsp;
    float4 sc = ((const float4*)g_scale)[lane];
    float4 sh = ((const float4*)g_shift)[lane];

    #define BNZ(v) do { \
        (v).x = fmaxf(fmaf((v).x, sc.x, sh.x), 0.f); \
        (v).y = fmaxf(fmaf((v).y, sc.y, sh.y), 0.f); \
        (v).z = fmaxf(fmaf((v).z, sc.z, sh.z), 0.f); \
        (v).w = fmaxf(fmaf((v).w, sc.w, sh.w), 0.f); } while (0)

    float4 acc = __ldg((const float4*)(g_h + (size_t)gw * DD) + lane);
    BNZ(acc);
    acc.x *= e; acc.y *= e; acc.z *= e; acc.w *= e;
    int beg = __ldg(&g_off[gw]);
    int end = __ldg(&g_off[gw + 1]);
    int j = beg;
    for (; j + 4 <= end; j += 4) {
        int s0 = __ldg(&g_csr[j]);
        int s1 = __ldg(&g_csr[j + 1]);
        int s2 = __ldg(&g_csr[j + 2]);
        int s3 = __ldg(&g_csr[j + 3]);
        float4 v0 = __ldg((const float4*)(g_h + (size_t)s0 * DD) + lane);
        float4 v1 = __ldg((const float4*)(g_h + (size_t)s1 * DD) + lane);
        float4 v2 = __ldg((const float4*)(g_h + (size_t)s2 * DD) + lane);
        float4 v3 = __ldg((const float4*)(g_h + (size_t)s3 * DD) + lane);
        BNZ(v0); BNZ(v1); BNZ(v2); BNZ(v3);
        acc.x += (v0.x + v1.x) + (v2.x + v3.x);
        acc.y += (v0.y + v1.y) + (v2.y + v3.y);
        acc.z += (v0.z + v1.z) + (v2.z + v3.z);
        acc.w += (v0.w + v1.w) + (v2.w + v3.w);
    }
    for (; j < end; j++) {
        int s = __ldg(&g_csr[j]);
        float4 v = __ldg((const float4*)(g_h + (size_t)s * DD) + lane);
        BNZ(v);
        acc.x += v.x; acc.y += v.y; acc.z += v.z; acc.w += v.w;
    }
    #undef BNZ
    ((float4*)(g_agg + (size_t)gw * DD))[lane] = acc;
}

// ---------------- fused 2-GEMM MLP (fp32 FFMA) + BN stats + last-block BN finalize ----------------
__global__ void __launch_bounds__(256, 1) k_mlp(
    const float* __restrict__ Wa, const float* __restrict__ ba,
    const float* __restrict__ Wb, const float* __restrict__ bb,
    const float* __restrict__ gamma, const float* __restrict__ beta, int layer)
{
    extern __shared__ float sm[];
    float* sWa = sm;
    float* sWb = sm + 16384;
    float* sA  = sm + 32768;
    float* sT  = sm + 40960;
    float* sS  = sm + 49152;
    __shared__ int sLast;

    int tid = threadIdx.x;
    for (int i = tid; i < 4096; i += 256) {
        ((float4*)sWa)[i] = ((const float4*)Wa)[i];
        ((float4*)sWb)[i] = ((const float4*)Wb)[i];
    }
    sS[tid] = 0.0f;

    int tx = tid & 31;
    int ty = tid >> 5;
    float4 ba4 = *(const float4*)(ba + tx * 4);
    float4 bb4 = *(const float4*)(bb + tx * 4);
    __syncthreads();

    const int ntiles = (NN + 63) / 64;
    for (int t = blockIdx.x; t < ntiles; t += gridDim.x) {
        int row0 = t * 64;
        int rows = NN - row0; if (rows > 64) rows = 64;

        for (int i = tid; i < 2048; i += 256) {
            int r = i >> 5;
            float4 v = make_float4(0.f, 0.f, 0.f, 0.f);
            if (r < rows) v = ((const float4*)(g_agg + (size_t)(row0 + r) * DD))[i & 31];
            ((float4*)sA)[i] = v;
        }
        __syncthreads();

        float acc[8][4];
        #pragma unroll
        for (int r = 0; r < 8; r++) { acc[r][0] = ba4.x; acc[r][1] = ba4.y; acc[r][2] = ba4.z; acc[r][3] = ba4.w; }
        #pragma unroll 8
        for (int k = 0; k < DD; k++) {
            float4 w = ((const float4*)(sWa + k * DD))[tx];
            #pragma unroll
            for (int r = 0; r < 8; r++) {
                float a = sA[(ty * 8 + r) * DD + k];
                acc[r][0] = fmaf(a, w.x, acc[r][0]);
                acc[r][1] = fmaf(a, w.y, acc[r][1]);
                acc[r][2] = fmaf(a, w.z, acc[r][2]);
                acc[r][3] = fmaf(a, w.w, acc[r][3]);
            }
        }
        #pragma unroll
        for (int r = 0; r < 8; r++) {
            float4 v = make_float4(fmaxf(acc[r][0], 0.f), fmaxf(acc[r][1], 0.f),
                                   fmaxf(acc[r][2], 0.f), fmaxf(acc[r][3], 0.f));
            ((float4*)(sT + (ty * 8 + r) * DD))[tx] = v;
        }
        __syncthreads();

        #pragma unroll
        for (int r = 0; r < 8; r++) { acc[r][0] = bb4.x; acc[r][1] = bb4.y; acc[r][2] = bb4.z; acc[r][3] = bb4.w; }
        #pragma unroll 8
        for (int k = 0; k < DD; k++) {
            float4 w = ((const float4*)(sWb + k * DD))[tx];
            #pragma unroll
            for (int r = 0; r < 8; r++) {
                float a = sT[(ty * 8 + r) * DD + k];
                acc[r][0] = fmaf(a, w.x, acc[r][0]);
                acc[r][1] = fmaf(a, w.y, acc[r][1]);
                acc[r][2] = fmaf(a, w.z, acc[r][2]);
                acc[r][3] = fmaf(a, w.w, acc[r][3]);
            }
        }

        float s0 = 0.f, s1 = 0.f, s2 = 0.f, s3 = 0.f;
        float q0 = 0.f, q1 = 0.f, q2 = 0.f, q3 = 0.f;
        #pragma unroll
        for (int r = 0; r < 8; r++) {
            int rr = ty * 8 + r;
            if (rr < rows) {
                float4 v = make_float4(acc[r][0], acc[r][1], acc[r][2], acc[r][3]);
                ((float4*)(g_h + (size_t)(row0 + rr) * DD))[tx] = v;
                s0 += v.x; q0 += v.x * v.x;
                s1 += v.y; q1 += v.y * v.y;
                s2 += v.z; q2 += v.z * v.z;
                s3 += v.w; q3 += v.w * v.w;
            }
        }
        int c = tx * 4;
        atomicAdd(&sS[c + 0], s0); atomicAdd(&sS[128 + c + 0], q0);
        atomicAdd(&sS[c + 1], s1); atomicAdd(&sS[128 + c + 1], q1);
        atomicAdd(&sS[c + 2], s2); atomicAdd(&sS[128 + c + 2], q2);
        atomicAdd(&sS[c + 3], s3); atomicAdd(&sS[128 + c + 3], q3);
        __syncthreads();
    }
    // flush block stats
    atomicAdd(&g_stats[layer * 256 + tid], (double)sS[tid]);

    // last-block BN finalize
    if (tid == 0) {
        __threadfence();
        int old = atomicAdd(&g_mlp_ctr[layer], 1);
        sLast = (old == gridDim.x - 1);
    }
    __syncthreads();
    if (sLast) {
        __threadfence();
        if (tid < DD) {
            int c = tid;
            double s = g_stats[layer * 256 + c];
            double q = g_stats[layer * 256 + 128 + c];
            float m = (float)(s / (double)NN);
            float v = (float)(q / (double)NN) - m * m;
            float sc = gamma[c] * rsqrtf(v + BN_EPS_F);
            g_scale[c] = sc;
            g_shift[c] = beta[c] - m * sc;
        }
    }
}

// ---------------- final: persistent; z2 = relu(bn(h2)); logits; softmax ----------------
#define FIN_TILES ((NN + 15) / 16)
__global__ void __launch_bounds__(128) k_final(
    const float* __restrict__ Wout, const float* __restrict__ log_tau,
    float* __restrict__ out)
{
    __shared__ float sW[DD * KK];
    __shared__ float sZ[16 * DD];
    int tid = threadIdx.x;
    for (int i = tid; i < DD * KK / 4; i += 128)
        ((float4*)sW)[i] = ((const float4*)Wout)[i];

    int warp = tid >> 5, lane = tid & 31;
    float inv_tau = expf(-*log_tau);

    for (int t = blockIdx.x; t < FIN_TILES; t += gridDim.x) {
        int row0 = t * 16;
        __syncthreads();
        for (int i = tid; i < 16 * DD / 4; i += 128) {
            int r = i >> 5;
            int c4 = i & 31;
            float4 v = make_float4(0.f, 0.f, 0.f, 0.f);
            int row = row0 + r;
            if (row < NN) {
                float4 hv = ((const float4*)(g_h + (size_t)row * DD))[c4];
                float4 sc = ((const float4*)g_scale)[c4];
                float4 sh = ((const float4*)g_shift)[c4];
                v.x = fmaxf(fmaf(hv.x, sc.x, sh.x), 0.f);
                v.y = fmaxf(fmaf(hv.y, sc.y, sh.y), 0.f);
                v.z = fmaxf(fmaf(hv.z, sc.z, sh.z), 0.f);
                v.w = fmaxf(fmaf(hv.w, sc.w, sh.w), 0.f);
            }
            ((float4*)sZ)[i] = v;
        }
        __syncthreads();

        float acc[4][2];
        #pragma unroll
        for (int r = 0; r < 4; r++) { acc[r][0] = 0.f; acc[r][1] = 0.f; }
        #pragma unroll 4
        for (int k = 0; k < DD; k++) {
            float w0 = sW[k * KK + lane];
            float w1 = sW[k * KK + 32 + lane];
            #pragma unroll
            for (int r = 0; r < 4; r++) {
                float z = sZ[(warp * 4 + r) * DD + k];
                acc[r][0] = fmaf(z, w0, acc[r][0]);
                acc[r][1] = fmaf(z, w1, acc[r][1]);
            }
        }

        #pragma unroll
        for (int r = 0; r < 4; r++) {
            int row = row0 + warp * 4 + r;
            if (row >= NN) continue;
            float l0 = acc[r][0], l1 = acc[r][1];
            out[(size_t)NN * KK + (size_t)row * KK + lane]      = l0;
            out[(size_t)NN * KK + (size_t)row * KK + 32 + lane] = l1;
            float a0 = l0 * inv_tau, a1 = l1 * inv_tau;
            float m = fmaxf(a0, a1);
            #pragma unroll
            for (int o = 16; o > 0; o >>= 1) m = fmaxf(m, __shfl_xor_sync(0xffffffffu, m, o));
            float e0 = expf(a0 - m), e1 = expf(a1 - m);
            float s = e0 + e1;
            #pragma unroll
            for (int o = 16; o > 0; o >>= 1) s += __shfl_xor_sync(0xffffffffu, s, o);
            float inv = 1.0f / s;
            out[(size_t)row * KK + lane]      = e0 * inv;
            out[(size_t)row * KK + 32 + lane] = e1 * inv;
        }
    }
}

// ---------------- launch ----------------
extern "C" void kernel_launch(void* const* d_in, const int* in_sizes, int n_in,
                              void* d_out, int out_size) {
    const float* x      = (const float*)d_in[0];
    const int*   ei     = (const int*)d_in[1];
    const float* W1a    = (const float*)d_in[2];
    const float* b1a    = (const float*)d_in[3];
    const float* W1b    = (const float*)d_in[4];
    const float* b1b    = (const float*)d_in[5];
    const float* eps1   = (const float*)d_in[6];
    const float* gamma1 = (const float*)d_in[7];
    const float* beta1  = (const float*)d_in[8];
    const float* W2a    = (const float*)d_in[9];
    const float* b2a    = (const float*)d_in[10];
    const float* W2b    = (const float*)d_in[11];
    const float* b2b    = (const float*)d_in[12];
    const float* eps2   = (const float*)d_in[13];
    const float* gamma2 = (const float*)d_in[14];
    const float* beta2  = (const float*)d_in[15];
    const float* Wout   = (const float*)d_in[16];
    const float* ltau   = (const float*)d_in[17];
    float* out = (float*)d_out;

    const int MLP_SMEM = 49408 * 4;   // 197632 B
    cudaFuncSetAttribute(k_mlp, cudaFuncAttributeMaxDynamicSharedMemorySize, MLP_SMEM);

    int n_blocks  = (NN + 255) / 256;
    int e4_blocks = (EE / 4 + 255) / 256;   // 782
    int gw_blocks = (NN * 32 + 255) / 256;

    // CSR build (vectorized hist/permute, fused single-kernel scan)
    k_zero<<<n_blocks, 256>>>();
    k_hist<<<e4_blocks, 256>>>(ei);
    k_scan<<<SCAN_NB, 1024>>>();
    k_permute<<<e4_blocks, 256>>>(ei);

    // layer 1 (BN finalize fused into last MLP block)
    k_gather<<<gw_blocks, 256>>>(x, eps1);
    k_mlp<<<148, 256, MLP_SMEM>>>(W1a, b1a, W1b, b1b, gamma1, beta1, 0);

    // layer 2
    k_gather_bn<<<gw_blocks, 256>>>(eps2);
    k_mlp<<<148, 256, MLP_SMEM>>>(W2a, b2a, W2b, b2b, gamma2, beta2, 1);

    k_final<<<592, 128>>>(Wout, ltau, out);
}